// round 14
// baseline (speedup 1.0000x reference)
#include <cuda_runtime.h>

#define BS   16
#define NA   8400
#define NG   64
#define NC   80
#define NTOP 10
#define CAP  256          // max in-gts anchors per gt
#define EPSF 1e-9f
#define NBX  16           // 16x16 spatial bins of 40px over 640x640
#define NBINS 256
#define BINW_INV (1.0f/40.0f)
#define FBLK 132          // k_finish blocks (<148 SMs => all resident => barrier safe)

// Output layout (float32, concatenated flat):
#define OFF_L 0
#define OFF_B 134400
#define OFF_S 672000
#define OFF_M 11424000

// -------- scratch (device globals; no allocation allowed) ----------
__device__ unsigned long long g_mask[BS * NA];   // bit j set => gt j pre-assigned anchor a
__device__ float  g_pos_align[BS * NG];
__device__ float  g_pos_over [BS * NG];
__device__ float4 g_binned[NA];                  // {x, y, idx-as-bits, 0} counting-sorted by bin
__device__ int    g_binstart[NBINS + 1];
__device__ int    g_bar_count;                   // self-resets each barrier
__device__ int    g_bar_sense;                   // toggles; replay-safe

__device__ __forceinline__ float iou_f(float4 g, float4 p, float area1, float area2) {
    float lx = fmaxf(g.x, p.x), ly = fmaxf(g.y, p.y);
    float rx = fminf(g.z, p.z), ry = fminf(g.w, p.w);
    float ov = fmaxf(rx - lx, 0.f) * fmaxf(ry - ly, 0.f);
    return ov / (area1 + area2 - ov + EPSF);
}

__device__ __forceinline__ float dmin_f(float4 g, float x, float y) {
    return fminf(fminf(x - g.x, y - g.y), fminf(g.z - x, g.w - y));
}

__device__ __forceinline__ float area_f(float4 g) {
    return fmaxf(g.z - g.x, 0.f) * fmaxf(g.w - g.y, 0.f);
}

// Sense-reversal grid barrier. FBLK=132 blocks x 1024 thr, 1 block/SM => all
// resident. Counter self-resets; sense toggles across graph replays but every
// block samples it before its own first arrival (flip requires ALL blocks).
__device__ __forceinline__ void grid_barrier(int* my_sense) {
    __syncthreads();
    if (threadIdx.x == 0) {
        __threadfence();
        int old = atomicAdd(&g_bar_count, 1);
        if (old == FBLK - 1) {
            g_bar_count = 0;
            __threadfence();
            *(volatile int*)&g_bar_sense = 1 - *my_sense;
        } else {
            while (*(volatile int*)&g_bar_sense == *my_sense) __nanosleep(64);
        }
        __threadfence();
    }
    __syncthreads();
    *my_sense = 1 - *my_sense;
}

// -------- K0: blocks 0-15 = parallel strip sorters (one bin-row each);
//              blocks 16-147 = scratch init + background defaults -----------
__global__ __launch_bounds__(1024) void k_bin(
    const float2* __restrict__ anc,
    const int*    __restrict__ gt_labels,
    const float4* __restrict__ gt_bboxes,
    float* __restrict__ out)
{
    const int tid = threadIdx.x;

    if (blockIdx.x < NBX) {
        // strip sorter for bin-row r: rows partition anchors by y, so this
        // row's global base = #anchors with by < r, computable locally.
        const int r = blockIdx.x;
        __shared__ int s_cnt[NBX];
        __shared__ int s_off[NBX];
        __shared__ int s_below;

        if (tid < NBX) s_cnt[tid] = 0;
        if (tid == 0) s_below = 0;
        __syncthreads();

        int below = 0;
        for (int i = tid; i < NA; i += 1024) {
            float2 ap = anc[i];
            int by = min(NBX - 1, (int)(ap.y * BINW_INV));
            if (by < r) below++;
            else if (by == r) {
                int bx = min(NBX - 1, (int)(ap.x * BINW_INV));
                atomicAdd(&s_cnt[bx], 1);
            }
        }
        #pragma unroll
        for (int off = 16; off; off >>= 1)
            below += __shfl_xor_sync(0xffffffffu, below, off);
        if ((tid & 31) == 0) atomicAdd(&s_below, below);
        __syncthreads();

        if (tid == 0) {
            int acc = s_below;
            #pragma unroll
            for (int c = 0; c < NBX; c++) {
                s_off[c] = acc;
                g_binstart[r * NBX + c] = acc;
                acc += s_cnt[c];
            }
            if (r == NBX - 1) g_binstart[NBINS] = NA;
        }
        __syncthreads();

        for (int i = tid; i < NA; i += 1024) {
            float2 ap = anc[i];
            int by = min(NBX - 1, (int)(ap.y * BINW_INV));
            if (by == r) {
                int bx = min(NBX - 1, (int)(ap.x * BINW_INV));
                int pos = atomicAdd(&s_off[bx], 1);
                g_binned[pos] = make_float4(ap.x, ap.y, __int_as_float(i), 0.f);
            }
        }
        return;
    }

    // -------- defaults / scratch init (blocks 16..147) --------
    const int step = (gridDim.x - NBX) * 1024;
    const int base = (blockIdx.x - NBX) * 1024 + tid;
    const float4 z = make_float4(0.f, 0.f, 0.f, 0.f);

    // zero g_mask (134400 u64)
    for (int i = base; i < BS * NA; i += step) g_mask[i] = 0ull;
    // fg_mask = 0 (33600 float4)
    float4* fm = (float4*)(out + OFF_M);
    for (int i = base; i < BS * NA / 4; i += step) fm[i] = z;
    // target_scores = 0 (2,688,000 float4)
    float4* os = (float4*)(out + OFF_S);
    for (int i = base; i < BS * NA * (NC / 4); i += step) os[i] = z;
    // target_labels default = labels[b][0] (33600 float4; 2100 per batch)
    float4* lb = (float4*)(out + OFF_L);
    for (int i = base; i < BS * NA / 4; i += step) {
        int b = i / (NA / 4);
        float v = (float)gt_labels[b * NG];
        lb[i] = make_float4(v, v, v, v);
    }
    // target_bboxes default = gt_bboxes[b][0] (134400 float4)
    float4* bb = (float4*)(out + OFF_B);
    for (int i = base; i < BS * NA; i += step) {
        int b = i / NA;
        bb[i] = gt_bboxes[b * NG];
    }
    if (blockIdx.x == NBX) { g_pos_align[tid] = 0.f; g_pos_over[tid] = 0.f; }
}

// -------- K1: per-(b,j) warp — binned candidates + exact stable top-10 --------
__global__ __launch_bounds__(256) void k_gather(
    const float*  __restrict__ pd_scores,
    const float4* __restrict__ pd_bboxes,
    const float2* __restrict__ anc,
    const int*    __restrict__ gt_labels,
    const float4* __restrict__ gt_bboxes)
{
    __shared__ float s_cv[8][CAP];
    __shared__ int   s_ci[8][CAP];
    __shared__ int   s_cnt[8];
    __shared__ float s_tv[8][NTOP];
    __shared__ int   s_ti[8][NTOP];

    const int w    = threadIdx.x >> 5;
    const int lane = threadIdx.x & 31;
    const int b = blockIdx.x >> 3;
    const int j = ((blockIdx.x & 7) << 3) + w;

    if (lane == 0) s_cnt[w] = 0;
    __syncwarp();

    const float4 g = gt_bboxes[b * NG + j];
    const int lbl  = gt_labels[b * NG + j];
    const float area1 = fmaxf(g.z - g.x, 0.f) * fmaxf(g.w - g.y, 0.f);
    const float4* pb = pd_bboxes + b * NA;
    const float*  sb = pd_scores + (long long)b * NA * NC;

    const int bx0 = max(0, min(NBX - 1, (int)(g.x * BINW_INV)));
    const int bx1 = max(0, min(NBX - 1, (int)(g.z * BINW_INV)));
    const int by0 = max(0, min(NBX - 1, (int)(g.y * BINW_INV)));
    const int by1 = max(0, min(NBX - 1, (int)(g.w * BINW_INV)));

    for (int by = by0; by <= by1; by++) {
        const int lo = g_binstart[by * NBX + bx0];
        const int hi = g_binstart[by * NBX + bx1 + 1];
        for (int base = lo; base < hi; base += 32) {
            int t = base + lane;
            bool in = false; float al = 0.f; int idx = 0;
            if (t < hi) {
                float4 c = g_binned[t];
                idx = __float_as_int(c.z);
                if (dmin_f(g, c.x, c.y) > EPSF) {
                    in = true;
                    float4 p = pb[idx];
                    float area2 = fmaxf(p.z - p.x, 0.f) * fmaxf(p.w - p.y, 0.f);
                    float iou = iou_f(g, p, area1, area2);
                    float sc = sb[(long long)idx * NC + lbl];
                    float o2 = iou * iou;
                    al = sqrtf(sc) * (o2 * o2 * o2);
                }
            }
            unsigned m = __ballot_sync(0xffffffffu, in);
            if (m) {
                int leader = __ffs(m) - 1;
                int r = __popc(m & ((1u << lane) - 1u));
                int bpos = 0;
                if (lane == leader) bpos = atomicAdd(&s_cnt[w], __popc(m));
                bpos = __shfl_sync(0xffffffffu, bpos, leader);
                if (in) {
                    int slot = bpos + r;
                    if (slot < CAP) { s_cv[w][slot] = al; s_ci[w][slot] = idx; }
                }
            }
        }
    }
    __syncwarp();
    const int cnt = min(s_cnt[w], CAP);

    // 10 rounds of warp argmax over candidates; ties -> lowest anchor index
    // (matches jax.lax.top_k stability; order-independent of fill order).
    for (int r = 0; r < NTOP; r++) {
        float bv = -1.f; int bi = 0x7fffffff; int bs_ = -1;
        for (int c = lane; c < cnt; c += 32) {
            float v = s_cv[w][c]; int i = s_ci[w][c];
            if (v > bv || (v == bv && i < bi)) { bv = v; bi = i; bs_ = c; }
        }
        #pragma unroll
        for (int off = 16; off; off >>= 1) {
            float v = __shfl_xor_sync(0xffffffffu, bv, off);
            int   i = __shfl_xor_sync(0xffffffffu, bi, off);
            int   s = __shfl_xor_sync(0xffffffffu, bs_, off);
            if (v > bv || (v == bv && i < bi)) { bv = v; bi = i; bs_ = s; }
        }
        if (lane == 0) {
            s_tv[w][r] = bv; s_ti[w][r] = bi;
            if (bs_ >= 0) s_cv[w][bs_] = -1.f;
        }
        __syncwarp();
    }

    if (s_tv[w][0] <= EPSF) return;   // invalid row (covers cnt==0 / all-zero)

    int P = 0;
    #pragma unroll
    for (int r = 0; r < NTOP; r++) P += (s_tv[w][r] > 0.f) ? 1 : 0;

    // positive winners are in-gts by construction -> scatter bits
    if (lane < P)
        atomicOr(&g_mask[b * NA + s_ti[w][lane]], 1ull << j);

    // zero-value fillers: the (10-P) lowest-index zero-valued entries are
    // provably within anchor indices [0, 10). Evaluate first 32 in parallel.
    if (P < NTOP) {
        int slots = NTOP - P;
        int i = lane;                       // anchor index = lane (0..31)
        float2 ap = anc[i];
        bool ing = dmin_f(g, ap.x, ap.y) > EPSF;
        float al = 0.f;
        if (ing) {
            float4 p = pb[i];
            float area2 = fmaxf(p.z - p.x, 0.f) * fmaxf(p.w - p.y, 0.f);
            float iou = iou_f(g, p, area1, area2);
            float sc  = sb[(long long)i * NC + lbl];
            float o2 = iou * iou;
            al = sqrtf(sc) * (o2 * o2 * o2);
        }
        bool isZero = !(al > 0.f);          // positives are already in the top-k
        unsigned zm = __ballot_sync(0xffffffffu, isZero);
        int rank = __popc(zm & ((1u << lane) - 1u));
        if (isZero && rank < slots && ing)
            atomicOr(&g_mask[b * NA + i], 1ull << j);
    }
}

// -------- K2: assign (fg only) + barrier + norm scatter, one anchor/thread ---
__global__ __launch_bounds__(1024, 1) void k_finish(
    const float*  __restrict__ pd_scores,
    const float4* __restrict__ pd_bboxes,
    const int*    __restrict__ gt_labels,
    const float4* __restrict__ gt_bboxes,
    float* __restrict__ out)
{
    const int i = blockIdx.x * 1024 + threadIdx.x;
    const bool valid = i < BS * NA;
    int my_sense = *(volatile int*)&g_bar_sense;

    // ---- Phase A: per-anchor assignment (fg only; defaults pre-written) ----
    float al = 0.f; int enc = -1; int bq = 0;
    if (valid) {
        const int b = i / NA;
        bq = b;
        unsigned long long m = g_mask[i];
        if (m) {
            const float4* gtb = gt_bboxes + b * NG;
            float4 p = pd_bboxes[i];
            float area2 = area_f(p);
            int fg0 = __popcll(m);
            int tgt;
            if (fg0 == 1) {
                tgt = __ffsll((long long)m) - 1;
            } else {
                // argmax over ALL gts of IoU (first-occurrence ties, jnp.argmax)
                float mx = -1.f; tgt = 0;
                #pragma unroll 8
                for (int jj = 0; jj < NG; jj++) {
                    float4 gj = gtb[jj];
                    float v = iou_f(gj, p, area_f(gj), area2);
                    if (v > mx) { mx = v; tgt = jj; }
                }
            }
            float4 gb = gtb[tgt];
            int lbl = gt_labels[b * NG + tgt];
            float ovl = iou_f(gb, p, area_f(gb), area2);
            float sc = pd_scores[(long long)i * NC + lbl];
            float o2 = ovl * ovl;
            al = sqrtf(sc) * (o2 * o2 * o2);
            atomicMax((int*)&g_pos_align[b * NG + tgt], __float_as_int(al));
            atomicMax((int*)&g_pos_over [b * NG + tgt], __float_as_int(ovl));
            out[OFF_L + i] = (float)lbl;
            ((float4*)(out + OFF_B))[i] = gb;
            out[OFF_M + i] = 1.f;
            enc = tgt | (lbl << 6);
        }
    }

    grid_barrier(&my_sense);

    // ---- Phase B: norm + single scattered store per fg anchor ----
    if (enc >= 0) {
        int tg = enc & 63, lbl = enc >> 6;
        float po = __ldcg(&g_pos_over [bq * NG + tg]);
        float pa = __ldcg(&g_pos_align[bq * NG + tg]);
        float nrm = al * po / (pa + EPSF);
        out[OFF_S + (long long)i * NC + lbl] = nrm;
    }
}

extern "C" void kernel_launch(void* const* d_in, const int* in_sizes, int n_in,
                              void* d_out, int out_size)
{
    const float*  pd_scores = (const float*) d_in[0];
    const float4* pd_bboxes = (const float4*)d_in[1];
    const float2* anc       = (const float2*)d_in[2];
    const int*    gt_labels = (const int*)   d_in[3];
    const float4* gt_bboxes = (const float4*)d_in[4];
    float* out = (float*)d_out;

    k_bin    <<<148, 1024>>>(anc, gt_labels, gt_bboxes, out);
    k_gather <<<BS * 8, 256>>>(pd_scores, pd_bboxes, anc, gt_labels, gt_bboxes);
    k_finish <<<FBLK, 1024>>>(pd_scores, pd_bboxes, gt_labels, gt_bboxes, out);
}

// round 15
// speedup vs baseline: 1.2028x; 1.2028x over previous
#include <cuda_runtime.h>

#define BS   16
#define NA   8400
#define NG   64
#define NC   80
#define NTOP 10
#define CAP  256          // max in-gts anchors per gt
#define EPSF 1e-9f
#define NBX  16           // 16x16 spatial bins of 40px over 640x640
#define NBINS 256
#define BINW_INV (1.0f/40.0f)

// Output layout (float32, concatenated flat):
#define OFF_L 0
#define OFF_B 134400
#define OFF_S 672000
#define OFF_M 11424000

// -------- scratch (device globals; no allocation allowed) ----------
__device__ unsigned long long g_mask[BS * NA];   // bit j set => gt j pre-assigned anchor a
__device__ float  g_pos_align[BS * NG];
__device__ float  g_pos_over [BS * NG];
__device__ float  g_al [BS * NA];
__device__ int    g_tgt[BS * NA];                // -1 = background, else tgt | (label<<6)
__device__ float4 g_binned[NA];                  // {x, y, idx-as-bits, 0} counting-sorted by bin
__device__ int    g_binstart[NBINS + 1];

__device__ __forceinline__ float iou_f(float4 g, float4 p, float area1, float area2) {
    float lx = fmaxf(g.x, p.x), ly = fmaxf(g.y, p.y);
    float rx = fminf(g.z, p.z), ry = fminf(g.w, p.w);
    float ov = fmaxf(rx - lx, 0.f) * fmaxf(ry - ly, 0.f);
    return ov / (area1 + area2 - ov + EPSF);
}

__device__ __forceinline__ float dmin_f(float4 g, float x, float y) {
    return fminf(fminf(x - g.x, y - g.y), fminf(g.z - x, g.w - y));
}

// -------- K0: blocks 0-15 = parallel strip sorters (one bin-row each);
//              blocks 16-295 = scratch init + background defaults.
//              296 blocks x 1024 thr = 2 CTAs/SM -> ~2x store-MLP ----------
__global__ __launch_bounds__(1024) void k_bin(
    const float2* __restrict__ anc,
    const int*    __restrict__ gt_labels,
    const float4* __restrict__ gt_bboxes,
    float* __restrict__ out)
{
    const int tid = threadIdx.x;

    if (blockIdx.x < NBX) {
        // strip sorter for bin-row r: rows partition anchors by y, so this
        // row's global base = #anchors with by < r, computable locally.
        const int r = blockIdx.x;
        __shared__ int s_cnt[NBX];
        __shared__ int s_off[NBX];
        __shared__ int s_below;

        if (tid < NBX) s_cnt[tid] = 0;
        if (tid == 0) s_below = 0;
        __syncthreads();

        int below = 0;
        for (int i = tid; i < NA; i += 1024) {
            float2 ap = anc[i];
            int by = min(NBX - 1, (int)(ap.y * BINW_INV));
            if (by < r) below++;
            else if (by == r) {
                int bx = min(NBX - 1, (int)(ap.x * BINW_INV));
                atomicAdd(&s_cnt[bx], 1);
            }
        }
        #pragma unroll
        for (int off = 16; off; off >>= 1)
            below += __shfl_xor_sync(0xffffffffu, below, off);
        if ((tid & 31) == 0) atomicAdd(&s_below, below);
        __syncthreads();

        if (tid == 0) {
            int acc = s_below;
            #pragma unroll
            for (int c = 0; c < NBX; c++) {
                s_off[c] = acc;
                g_binstart[r * NBX + c] = acc;
                acc += s_cnt[c];
            }
            if (r == NBX - 1) g_binstart[NBINS] = NA;
        }
        __syncthreads();

        for (int i = tid; i < NA; i += 1024) {
            float2 ap = anc[i];
            int by = min(NBX - 1, (int)(ap.y * BINW_INV));
            if (by == r) {
                int bx = min(NBX - 1, (int)(ap.x * BINW_INV));
                int pos = atomicAdd(&s_off[bx], 1);
                g_binned[pos] = make_float4(ap.x, ap.y, __int_as_float(i), 0.f);
            }
        }
        return;
    }

    // -------- defaults / scratch init (blocks 16..295) --------
    const int step = (gridDim.x - NBX) * 1024;
    const int base = (blockIdx.x - NBX) * 1024 + tid;
    const float4 z = make_float4(0.f, 0.f, 0.f, 0.f);

    // zero g_mask (134400 u64)
    for (int i = base; i < BS * NA; i += step) g_mask[i] = 0ull;
    // g_tgt = -1 (33600 int4)
    int4* t4 = (int4*)g_tgt;
    for (int i = base; i < BS * NA / 4; i += step)
        t4[i] = make_int4(-1, -1, -1, -1);
    // fg_mask = 0 (33600 float4)
    float4* fm = (float4*)(out + OFF_M);
    for (int i = base; i < BS * NA / 4; i += step) fm[i] = z;
    // target_scores = 0 (2,688,000 float4)
    float4* os = (float4*)(out + OFF_S);
    for (int i = base; i < BS * NA * (NC / 4); i += step) os[i] = z;
    // target_labels default = labels[b][0] (33600 float4; 2100 per batch)
    float4* lb = (float4*)(out + OFF_L);
    for (int i = base; i < BS * NA / 4; i += step) {
        int b = i / (NA / 4);
        float v = (float)gt_labels[b * NG];
        lb[i] = make_float4(v, v, v, v);
    }
    // target_bboxes default = gt_bboxes[b][0] (134400 float4)
    float4* bb = (float4*)(out + OFF_B);
    for (int i = base; i < BS * NA; i += step) {
        int b = i / NA;
        bb[i] = gt_bboxes[b * NG];
    }
    if (blockIdx.x == NBX) { g_pos_align[tid] = 0.f; g_pos_over[tid] = 0.f; }
}

// -------- K1: per-(b,j) warp — binned candidates + exact stable top-10 --------
__global__ __launch_bounds__(256) void k_gather(
    const float*  __restrict__ pd_scores,
    const float4* __restrict__ pd_bboxes,
    const float2* __restrict__ anc,
    const int*    __restrict__ gt_labels,
    const float4* __restrict__ gt_bboxes)
{
    __shared__ float s_cv[8][CAP];
    __shared__ int   s_ci[8][CAP];
    __shared__ int   s_cnt[8];
    __shared__ float s_tv[8][NTOP];
    __shared__ int   s_ti[8][NTOP];

    const int w    = threadIdx.x >> 5;
    const int lane = threadIdx.x & 31;
    const int b = blockIdx.x >> 3;
    const int j = ((blockIdx.x & 7) << 3) + w;

    if (lane == 0) s_cnt[w] = 0;
    __syncwarp();

    const float4 g = gt_bboxes[b * NG + j];
    const int lbl  = gt_labels[b * NG + j];
    const float area1 = fmaxf(g.z - g.x, 0.f) * fmaxf(g.w - g.y, 0.f);
    const float4* pb = pd_bboxes + b * NA;
    const float*  sb = pd_scores + (long long)b * NA * NC;

    const int bx0 = max(0, min(NBX - 1, (int)(g.x * BINW_INV)));
    const int bx1 = max(0, min(NBX - 1, (int)(g.z * BINW_INV)));
    const int by0 = max(0, min(NBX - 1, (int)(g.y * BINW_INV)));
    const int by1 = max(0, min(NBX - 1, (int)(g.w * BINW_INV)));

    for (int by = by0; by <= by1; by++) {
        const int lo = g_binstart[by * NBX + bx0];
        const int hi = g_binstart[by * NBX + bx1 + 1];
        for (int base = lo; base < hi; base += 32) {
            int t = base + lane;
            bool in = false; float al = 0.f; int idx = 0;
            if (t < hi) {
                float4 c = g_binned[t];
                idx = __float_as_int(c.z);
                if (dmin_f(g, c.x, c.y) > EPSF) {
                    in = true;
                    float4 p = pb[idx];
                    float area2 = fmaxf(p.z - p.x, 0.f) * fmaxf(p.w - p.y, 0.f);
                    float iou = iou_f(g, p, area1, area2);
                    float sc = sb[(long long)idx * NC + lbl];
                    float o2 = iou * iou;
                    al = sqrtf(sc) * (o2 * o2 * o2);
                }
            }
            unsigned m = __ballot_sync(0xffffffffu, in);
            if (m) {
                int leader = __ffs(m) - 1;
                int r = __popc(m & ((1u << lane) - 1u));
                int bpos = 0;
                if (lane == leader) bpos = atomicAdd(&s_cnt[w], __popc(m));
                bpos = __shfl_sync(0xffffffffu, bpos, leader);
                if (in) {
                    int slot = bpos + r;
                    if (slot < CAP) { s_cv[w][slot] = al; s_ci[w][slot] = idx; }
                }
            }
        }
    }
    __syncwarp();
    const int cnt = min(s_cnt[w], CAP);

    // 10 rounds of warp argmax over candidates; ties -> lowest anchor index
    // (matches jax.lax.top_k stability; order-independent of fill order).
    for (int r = 0; r < NTOP; r++) {
        float bv = -1.f; int bi = 0x7fffffff; int bs_ = -1;
        for (int c = lane; c < cnt; c += 32) {
            float v = s_cv[w][c]; int i = s_ci[w][c];
            if (v > bv || (v == bv && i < bi)) { bv = v; bi = i; bs_ = c; }
        }
        #pragma unroll
        for (int off = 16; off; off >>= 1) {
            float v = __shfl_xor_sync(0xffffffffu, bv, off);
            int   i = __shfl_xor_sync(0xffffffffu, bi, off);
            int   s = __shfl_xor_sync(0xffffffffu, bs_, off);
            if (v > bv || (v == bv && i < bi)) { bv = v; bi = i; bs_ = s; }
        }
        if (lane == 0) {
            s_tv[w][r] = bv; s_ti[w][r] = bi;
            if (bs_ >= 0) s_cv[w][bs_] = -1.f;
        }
        __syncwarp();
    }

    if (s_tv[w][0] <= EPSF) return;   // invalid row (covers cnt==0 / all-zero)

    int P = 0;
    #pragma unroll
    for (int r = 0; r < NTOP; r++) P += (s_tv[w][r] > 0.f) ? 1 : 0;

    // positive winners are in-gts by construction -> scatter bits
    if (lane < P)
        atomicOr(&g_mask[b * NA + s_ti[w][lane]], 1ull << j);

    // zero-value fillers: the (10-P) lowest-index zero-valued entries are
    // provably within anchor indices [0, 10). Evaluate first 32 in parallel.
    if (P < NTOP) {
        int slots = NTOP - P;
        int i = lane;                       // anchor index = lane (0..31)
        float2 ap = anc[i];
        bool ing = dmin_f(g, ap.x, ap.y) > EPSF;
        float al = 0.f;
        if (ing) {
            float4 p = pb[i];
            float area2 = fmaxf(p.z - p.x, 0.f) * fmaxf(p.w - p.y, 0.f);
            float iou = iou_f(g, p, area1, area2);
            float sc  = sb[(long long)i * NC + lbl];
            float o2 = iou * iou;
            al = sqrtf(sc) * (o2 * o2 * o2);
        }
        bool isZero = !(al > 0.f);          // positives are already in the top-k
        unsigned zm = __ballot_sync(0xffffffffu, isZero);
        int rank = __popc(zm & ((1u << lane) - 1u));
        if (isZero && rank < slots && ing)
            atomicOr(&g_mask[b * NA + i], 1ull << j);
    }
}

// -------- K2: fg anchors only (defaults pre-written by k_bin) ----------------
__global__ __launch_bounds__(256) void k_assign(
    const float*  __restrict__ pd_scores,
    const float4* __restrict__ pd_bboxes,
    const int*    __restrict__ gt_labels,
    const float4* __restrict__ gt_bboxes,
    float* __restrict__ out)
{
    __shared__ float4 s_g [NG];
    __shared__ float  s_a1[NG];
    __shared__ int    s_l [NG];

    const int tid = threadIdx.x;
    const int b = blockIdx.y;
    const int a = blockIdx.x * 256 + tid;

    if (tid < NG) {
        float4 g = gt_bboxes[b * NG + tid];
        s_g[tid] = g;
        s_a1[tid] = fmaxf(g.z - g.x, 0.f) * fmaxf(g.w - g.y, 0.f);
        s_l[tid] = gt_labels[b * NG + tid];
    }
    __syncthreads();
    if (a >= NA) return;

    const int ia = b * NA + a;
    unsigned long long m = g_mask[ia];
    int fg0 = __popcll(m);
    if (fg0 == 0) return;                 // background: defaults already written

    float4 p = pd_bboxes[ia];
    float area2 = fmaxf(p.z - p.x, 0.f) * fmaxf(p.w - p.y, 0.f);
    int tgt;
    if (fg0 == 1) {
        tgt = __ffsll((long long)m) - 1;
    } else {
        // argmax over ALL gts of IoU (first occurrence ties, as jnp.argmax)
        float mx = -1.f; tgt = 0;
        #pragma unroll 8
        for (int jj = 0; jj < NG; jj++) {
            float v = iou_f(s_g[jj], p, s_a1[jj], area2);
            if (v > mx) { mx = v; tgt = jj; }
        }
    }
    float4 gb = s_g[tgt];
    int lbl = s_l[tgt];
    float ovl = iou_f(gb, p, s_a1[tgt], area2);
    float sc = pd_scores[(long long)ia * NC + lbl];
    float o2 = ovl * ovl;
    float al = sqrtf(sc) * (o2 * o2 * o2);
    atomicMax((int*)&g_pos_align[b * NG + tgt], __float_as_int(al));
    atomicMax((int*)&g_pos_over [b * NG + tgt], __float_as_int(ovl));
    out[OFF_L + ia] = (float)lbl;
    ((float4*)(out + OFF_B))[ia] = gb;
    out[OFF_M + ia] = 1.f;
    g_al[ia]  = al;
    g_tgt[ia] = tgt | (lbl << 6);
}

// -------- K3: per-fg-anchor norm scatter (scores pre-zeroed by k_bin) --------
__global__ __launch_bounds__(1024) void k_scatter(float* __restrict__ out) {
    int i = blockIdx.x * 1024 + threadIdx.x;
    if (i >= BS * NA) return;
    int t = g_tgt[i];
    if (t < 0) return;
    int tg = t & 63, lbl = t >> 6;
    int b = i / NA;
    float nrm = g_al[i] * g_pos_over[b * NG + tg] / (g_pos_align[b * NG + tg] + EPSF);
    out[OFF_S + (long long)i * NC + lbl] = nrm;
}

extern "C" void kernel_launch(void* const* d_in, const int* in_sizes, int n_in,
                              void* d_out, int out_size)
{
    const float*  pd_scores = (const float*) d_in[0];
    const float4* pd_bboxes = (const float4*)d_in[1];
    const float2* anc       = (const float2*)d_in[2];
    const int*    gt_labels = (const int*)   d_in[3];
    const float4* gt_bboxes = (const float4*)d_in[4];
    float* out = (float*)d_out;

    k_bin    <<<296, 1024>>>(anc, gt_labels, gt_bboxes, out);
    k_gather <<<BS * 8, 256>>>(pd_scores, pd_bboxes, anc, gt_labels, gt_bboxes);
    dim3 g2((NA + 255) / 256, BS);
    k_assign <<<g2, 256>>>(pd_scores, pd_bboxes, gt_labels, gt_bboxes, out);
    k_scatter<<<(BS * NA + 1023) / 1024, 1024>>>(out);
}